// round 15
// baseline (speedup 1.0000x reference)
#include <cuda_runtime.h>
#include <cuda_bf16.h>
#include <cstdint>

#define D_DIM 256
#define B_SZ  64
#define S_SZ  64
#define T_TOT 4096
#define CPAD_MAX 12288
#define NSPLIT 2

#define LOG2E 1.4426950408889634f

// ---------------------------------------------------------------------------
// Device scratch (no allocs allowed)
// ---------------------------------------------------------------------------
__device__ float         g_denom[2][T_TOT];
__device__ __nv_bfloat16 g_zsb[T_TOT * D_DIM];        // bf16, pre-scaled by log2(e)
__device__ __nv_bfloat16 g_emb[2][CPAD_MAX * D_DIM];  // bf16 gathered candidates
__device__ float         g_wt[2][CPAD_MAX];

// ---------------------------------------------------------------------------
// PTX helpers (baseline sm_80 features only — no 'a'-suffix ops)
// ---------------------------------------------------------------------------
__device__ __forceinline__ uint32_t smem_to_u32(const void* p) {
    uint32_t a;
    asm("{ .reg .u64 t; cvta.to.shared.u64 t, %1; cvt.u32.u64 %0, t; }" : "=r"(a) : "l"(p));
    return a;
}
#define CP_ASYNC16(s, g) \
    asm volatile("cp.async.cg.shared.global [%0], [%1], 16;" :: "r"(s), "l"(g) : "memory")
#define CP_COMMIT() asm volatile("cp.async.commit_group;" ::: "memory")
#define CP_WAIT0()  asm volatile("cp.async.wait_group 0;" ::: "memory")
#define CP_WAIT1()  asm volatile("cp.async.wait_group 1;" ::: "memory")

#define LDSM_X4(r0, r1, r2, r3, a) \
    asm volatile("ldmatrix.sync.aligned.m8n8.x4.shared.b16 {%0,%1,%2,%3}, [%4];" \
                 : "=r"(r0), "=r"(r1), "=r"(r2), "=r"(r3) : "r"(a))

#define MMA16816(d, a0, a1, a2, a3, b0, b1) \
    asm volatile("mma.sync.aligned.m16n8k16.row.col.f32.bf16.bf16.f32 " \
                 "{%0,%1,%2,%3},{%4,%5,%6,%7},{%8,%9},{%0,%1,%2,%3};" \
                 : "+f"((d)[0]), "+f"((d)[1]), "+f"((d)[2]), "+f"((d)[3]) \
                 : "r"(a0), "r"(a1), "r"(a2), "r"(a3), "r"(b0), "r"(b1))

__device__ __forceinline__ float ex2f(float x) {
    float y;
    asm("ex2.approx.f32 %0, %1;" : "=f"(y) : "f"(x));
    return y;
}

// ---------------------------------------------------------------------------
// Merged prologue: [0,512) convert zs + zero; [512, 512+Cpad_en/8) gather en;
// remainder gather fr.
// ---------------------------------------------------------------------------
__device__ __forceinline__ void gather_rows(
    const float* __restrict__ W, const int* __restrict__ pos,
    const int* __restrict__ neg, const float* __restrict__ kap,
    int P, int C, int Cpad, int lang, int blk)
{
    int wid = threadIdx.x >> 5, lane = threadIdx.x & 31;
    int r = blk * 8 + wid;
    if (r >= Cpad) return;
    __nv_bfloat16* dst = g_emb[lang] + (size_t)r * D_DIM + lane * 8;
    if (r >= C) {
        *(uint4*)dst = make_uint4(0, 0, 0, 0);
        if (lane == 0) g_wt[lang][r] = 0.0f;
        return;
    }
    int src; float w;
    if (r < P) { src = pos[r]; w = 1.0f; }
    else       { src = neg[r - P]; w = *kap; }
    const float4* p = (const float4*)(W + (size_t)src * D_DIM) + lane * 2;
    float4 a = p[0], b = p[1];
    __nv_bfloat162 p0 = __float22bfloat162_rn(make_float2(a.x, a.y));
    __nv_bfloat162 p1 = __float22bfloat162_rn(make_float2(a.z, a.w));
    __nv_bfloat162 p2 = __float22bfloat162_rn(make_float2(b.x, b.y));
    __nv_bfloat162 p3 = __float22bfloat162_rn(make_float2(b.z, b.w));
    uint4 v;
    v.x = *(uint32_t*)&p0; v.y = *(uint32_t*)&p1;
    v.z = *(uint32_t*)&p2; v.w = *(uint32_t*)&p3;
    *(uint4*)dst = v;
    if (lane == 0) g_wt[lang][r] = w;
}

__global__ __launch_bounds__(256) void prologue_kernel(
    const float* __restrict__ zs, float* __restrict__ out,
    const float* __restrict__ W_en, const int* __restrict__ pos_en,
    const int* __restrict__ neg_en, const float* __restrict__ kap_en,
    int P_en, int C_en, int Cpad_en,
    const float* __restrict__ W_fr, const int* __restrict__ pos_fr,
    const int* __restrict__ neg_fr, const float* __restrict__ kap_fr,
    int P_fr, int C_fr, int Cpad_fr)
{
    int b = blockIdx.x;
    if (b < 512) {
        int gid = b * 256 + threadIdx.x;
        if (gid < 2 * T_TOT) ((float*)g_denom)[gid] = 0.0f;
        if (gid < 2 * B_SZ) out[gid] = 0.0f;
        const float4* p = (const float4*)(zs) + gid * 2;
        float4 a = p[0], bb = p[1];
        __nv_bfloat162 p0 = __float22bfloat162_rn(make_float2(a.x * LOG2E, a.y * LOG2E));
        __nv_bfloat162 p1 = __float22bfloat162_rn(make_float2(a.z * LOG2E, a.w * LOG2E));
        __nv_bfloat162 p2 = __float22bfloat162_rn(make_float2(bb.x * LOG2E, bb.y * LOG2E));
        __nv_bfloat162 p3 = __float22bfloat162_rn(make_float2(bb.z * LOG2E, bb.w * LOG2E));
        uint4 v;
        v.x = *(uint32_t*)&p0; v.y = *(uint32_t*)&p1;
        v.z = *(uint32_t*)&p2; v.w = *(uint32_t*)&p3;
        *(uint4*)(g_zsb + (size_t)gid * 8) = v;
    } else if (b < 512 + Cpad_en / 8) {
        gather_rows(W_en, pos_en, neg_en, kap_en, P_en, C_en, Cpad_en, 0, b - 512);
    } else {
        gather_rows(W_fr, pos_fr, neg_fr, kap_fr, P_fr, C_fr, Cpad_fr, 1, b - 512 - Cpad_en / 8);
    }
}

// ---------------------------------------------------------------------------
// SMEM tile: 128 rows x 256 bf16 (512 B/row = 32 chunks of 16B). XOR swizzle.
// ---------------------------------------------------------------------------
__device__ __forceinline__ void cp_tile(uint32_t sdst, const __nv_bfloat16* __restrict__ src, int tid) {
    #pragma unroll
    for (int t = 0; t < 16; t++) {
        int id = tid + t * 256;
        int row = id >> 5, h = id & 31;
        uint32_t s = sdst + row * 512 + ((h ^ (row & 7)) << 4);
        CP_ASYNC16(s, (const void*)(src + (size_t)row * D_DIM + h * 8));
    }
}

// ---------------------------------------------------------------------------
// Denominator GEMM via bf16 mma.sync m16n8k16. Warp layout 4(M) x 2(N),
// warp tile 32x64. Combines BOTH validated partial fixes:
//   (1) A fragments register-resident, loaded once (low LDS bandwidth, R13)
//   (2) B fragments double-buffered in the k-loop: k-step s+1's 4 LDSMs issue
//       before step s's 16 MMAs, hiding the ~30cyc LDSM latency (R9).
// ---------------------------------------------------------------------------
__global__ __launch_bounds__(256, 1) void denom_mma_kernel(int Cpad_en, int Cpad_fr)
{
    extern __shared__ char smem[];
    uint32_t sA  = smem_to_u32(smem);
    uint32_t sB0 = sA + 65536;
    uint32_t sB1 = sB0 + 65536;

    const int tid = threadIdx.x;
    const int wid = tid >> 5, lane = tid & 31;
    const int lang = blockIdx.z;
    const int Cpad = lang ? Cpad_fr : Cpad_en;
    const int niters = Cpad / (128 * NSPLIT);
    const int tile0 = blockIdx.y * niters;
    const int tileM = blockIdx.x * 128;

    const __nv_bfloat16* __restrict__ Eb = g_emb[lang];
    const float* __restrict__ wtg = g_wt[lang];

    cp_tile(sA, g_zsb + (size_t)tileM * D_DIM, tid);
    CP_COMMIT();
    cp_tile(sB0, Eb + (size_t)tile0 * 128 * D_DIM, tid);
    CP_COMMIT();

    const int warpM = (wid >> 1) * 32;            // 4 M-warps: 0,32,64,96
    const int warpN = (wid & 1) * 64;             // 2 N-warps: 0,64
    const int g   = lane >> 3;
    const int rin = lane & 7;
    const int ga  = g >> 1;
    const int gb  = g & 1;
    const int a_row = rin + ((g & 1) << 3);
    const int b_row = rin + ((g >> 1) << 3);

    uint32_t bRowOff[4];
    #pragma unroll
    for (int nf2 = 0; nf2 < 4; nf2++)
        bRowOff[nf2] = (warpN + nf2 * 16 + b_row) * 512;

    // ---- Load A fragments once into registers (A constant for all iters) ----
    CP_WAIT1();          // A tile done (B0 may still be in flight)
    __syncthreads();
    uint32_t raR[2][16][4];
    {
        uint32_t aRow0 = sA + (warpM + 0 * 16 + a_row) * 512;
        uint32_t aRow1 = sA + (warpM + 1 * 16 + a_row) * 512;
        #pragma unroll
        for (int s = 0; s < 16; s++) {
            const uint32_t offA = (uint32_t)(((2 * s + ga) ^ rin) << 4);
            LDSM_X4(raR[0][s][0], raR[0][s][1], raR[0][s][2], raR[0][s][3], aRow0 + offA);
            LDSM_X4(raR[1][s][0], raR[1][s][1], raR[1][s][2], raR[1][s][3], aRow1 + offA);
        }
    }

    float rowacc[4];
    #pragma unroll
    for (int j = 0; j < 4; j++) rowacc[j] = 0.0f;

    for (int i = 0; i < niters; i++) {
        const int cur = i & 1;
        const uint32_t sBc = cur ? sB1 : sB0;
        if (i + 1 < niters) {
            cp_tile(cur ? sB0 : sB1, Eb + (size_t)(tile0 + i + 1) * 128 * D_DIM, tid);
            CP_COMMIT();
            CP_WAIT1();
        } else {
            CP_WAIT0();
        }
        __syncthreads();

        float cc[2][8][4];
        #pragma unroll
        for (int mf = 0; mf < 2; mf++)
            #pragma unroll
            for (int nf = 0; nf < 8; nf++)
                #pragma unroll
                for (int q = 0; q < 4; q++) cc[mf][nf][q] = 0.0f;

        // B-fragment double buffer: prefetch k-step s+1 during step s's MMAs.
        uint32_t rb[2][8][2];
        {
            const uint32_t offB0 = (uint32_t)((gb ^ rin) << 4);
            #pragma unroll
            for (int nf2 = 0; nf2 < 4; nf2++) {
                uint32_t r0, r1, r2, r3;
                LDSM_X4(r0, r1, r2, r3, sBc + bRowOff[nf2] + offB0);
                rb[0][nf2 * 2 + 0][0] = r0; rb[0][nf2 * 2 + 0][1] = r1;
                rb[0][nf2 * 2 + 1][0] = r2; rb[0][nf2 * 2 + 1][1] = r3;
            }
        }
        #pragma unroll
        for (int s = 0; s < 16; s++) {
            const int cb = s & 1, nb = cb ^ 1;
            if (s < 15) {
                const uint32_t offB = (uint32_t)(((2 * (s + 1) + gb) ^ rin) << 4);
                #pragma unroll
                for (int nf2 = 0; nf2 < 4; nf2++) {
                    uint32_t r0, r1, r2, r3;
                    LDSM_X4(r0, r1, r2, r3, sBc + bRowOff[nf2] + offB);
                    rb[nb][nf2 * 2 + 0][0] = r0; rb[nb][nf2 * 2 + 0][1] = r1;
                    rb[nb][nf2 * 2 + 1][0] = r2; rb[nb][nf2 * 2 + 1][1] = r3;
                }
            }
            #pragma unroll
            for (int mf = 0; mf < 2; mf++)
                #pragma unroll
                for (int nf = 0; nf < 8; nf++)
                    MMA16816(cc[mf][nf], raR[mf][s][0], raR[mf][s][1],
                             raR[mf][s][2], raR[mf][s][3],
                             rb[cb][nf][0], rb[cb][nf][1]);
        }

        // Fused epilogue (log2 domain): rowacc += wt[col] * 2^score
        const float* wtp = wtg + (size_t)(tile0 + i) * 128 + warpN + 2 * (lane & 3);
        #pragma unroll
        for (int nf = 0; nf < 8; nf++) {
            const float w0 = wtp[nf * 8], w1 = wtp[nf * 8 + 1];
            #pragma unroll
            for (int mf = 0; mf < 2; mf++) {
                rowacc[mf * 2 + 0] += w0 * ex2f(cc[mf][nf][0]) + w1 * ex2f(cc[mf][nf][1]);
                rowacc[mf * 2 + 1] += w0 * ex2f(cc[mf][nf][2]) + w1 * ex2f(cc[mf][nf][3]);
            }
        }
        __syncthreads();   // protect sBc against next iteration's prefetch
    }

    #pragma unroll
    for (int j = 0; j < 4; j++) {
        float v = rowacc[j];
        v += __shfl_xor_sync(0xffffffffu, v, 1);
        v += __shfl_xor_sync(0xffffffffu, v, 2);
        if ((lane & 3) == 0)
            atomicAdd(&g_denom[lang][tileM + warpM + (j >> 1) * 16 + (j & 1) * 8 + (lane >> 2)], v);
    }
}

// ---------------------------------------------------------------------------
// fr loss helpers (validated fp32 f32x2 path)
// ---------------------------------------------------------------------------
__device__ __forceinline__ void fma2(unsigned long long &d, unsigned long long a, unsigned long long b) {
    asm("fma.rn.f32x2 %0, %1, %2, %0;" : "+l"(d) : "l"(a), "l"(b));
}
__device__ __forceinline__ unsigned long long pack2(float lo, float hi) {
    unsigned long long r;
    asm("mov.b64 %0, {%1, %2};" : "=l"(r) : "f"(lo), "f"(hi));
    return r;
}
__device__ __forceinline__ void unpack2(unsigned long long v, float &lo, float &hi) {
    asm("mov.b64 {%0, %1}, %2;" : "=f"(lo), "=f"(hi) : "l"(v));
}

// ---------------------------------------------------------------------------
// Merged loss kernel: blocks [0,512) en (warp-per-token); [512,576) fr.
// ---------------------------------------------------------------------------
__global__ __launch_bounds__(256) void loss_kernel(
    const float* __restrict__ zs,
    const int* __restrict__ x_en, const float* __restrict__ en_mask,
    const float* __restrict__ W_en,
    const int* __restrict__ x_fr, const float* __restrict__ fr_mask,
    const float* __restrict__ W_fr,
    float* __restrict__ out)
{
    __shared__ float Fs[16][64];
    __shared__ float Zs[16][64];
    __shared__ int   fidx[64];
    __shared__ float invd[64];
    __shared__ float sred[64];
    __shared__ float sfin[64];

    if (blockIdx.x < 512) {
        int wid = threadIdx.x >> 5, lane = threadIdx.x & 31;
        int t = blockIdx.x * 8 + wid;
        const float4* z = (const float4*)(zs + (size_t)t * D_DIM) + lane * 2;
        const float4* w = (const float4*)(W_en + (size_t)x_en[t] * D_DIM) + lane * 2;
        float4 a0 = z[0], a1 = z[1], b0 = w[0], b1 = w[1];
        float s = a0.x * b0.x + a0.y * b0.y + a0.z * b0.z + a0.w * b0.w
                + a1.x * b1.x + a1.y * b1.y + a1.z * b1.z + a1.w * b1.w;
        #pragma unroll
        for (int o = 16; o > 0; o >>= 1) s += __shfl_xor_sync(0xffffffffu, s, o);
        if (lane == 0)
            atomicAdd(&out[t >> 6], (s - logf(g_denom[0][t])) * en_mask[t]);
        return;
    }

    int b = blockIdx.x - 512;
    int tid = threadIdx.x;
    int tx = tid & 15, ty = tid >> 4;
    int m0 = tx * 4, n0 = ty * 4;

    if (tid < 64) {
        fidx[tid] = x_fr[b * S_SZ + tid];
        invd[tid] = 1.0f / g_denom[1][b * S_SZ + tid];
    }
    __syncthreads();

    int lr  = tid >> 2;
    int lkc = (tid & 3) << 2;
    const float* frow = W_fr + (size_t)fidx[lr] * D_DIM + lkc;
    const float* zrow = zs   + (size_t)(b * S_SZ + lr) * D_DIM + lkc;

    unsigned long long acc2[2][4];
    #pragma unroll
    for (int p = 0; p < 2; p++)
        #pragma unroll
        for (int j = 0; j < 4; j++) acc2[p][j] = 0ull;

    for (int k0 = 0; k0 < D_DIM; k0 += 16) {
        float4 av = *(const float4*)(frow + k0);
        float4 bv = *(const float4*)(zrow + k0);
        __syncthreads();
        Fs[lkc+0][lr] = av.x; Fs[lkc+1][lr] = av.y;
        Fs[lkc+2][lr] = av.z; Fs[lkc+3][lr] = av.w;
        Zs[lkc+0][lr] = bv.x; Zs[lkc+1][lr] = bv.y;
        Zs[lkc+2][lr] = bv.z; Zs[lkc+3][lr] = bv.w;
        __syncthreads();
        #pragma unroll
        for (int k = 0; k < 16; k++) {
            ulonglong2 a = *(const ulonglong2*)&Fs[k][m0];
            float4     bq = *(const float4*)&Zs[k][n0];
            unsigned long long b0 = pack2(bq.x, bq.x);
            unsigned long long b1 = pack2(bq.y, bq.y);
            unsigned long long b2 = pack2(bq.z, bq.z);
            unsigned long long b3 = pack2(bq.w, bq.w);
            fma2(acc2[0][0], a.x, b0); fma2(acc2[0][1], a.x, b1);
            fma2(acc2[0][2], a.x, b2); fma2(acc2[0][3], a.x, b3);
            fma2(acc2[1][0], a.y, b0); fma2(acc2[1][1], a.y, b1);
            fma2(acc2[1][2], a.y, b2); fma2(acc2[1][3], a.y, b3);
        }
    }

    float w0 = invd[n0], w1 = invd[n0+1], w2 = invd[n0+2], w3 = invd[n0+3];
    float pm[4];
    #pragma unroll
    for (int p = 0; p < 2; p++) {
        float s0a,s0b,s1a,s1b,s2a,s2b,s3a,s3b;
        unpack2(acc2[p][0], s0a, s0b);
        unpack2(acc2[p][1], s1a, s1b);
        unpack2(acc2[p][2], s2a, s2b);
        unpack2(acc2[p][3], s3a, s3b);
        pm[2*p+0] = w0*__expf(s0a) + w1*__expf(s1a) + w2*__expf(s2a) + w3*__expf(s3a);
        pm[2*p+1] = w0*__expf(s0b) + w1*__expf(s1b) + w2*__expf(s2b) + w3*__expf(s3b);
    }

    __syncthreads();
    if (tid < 64) sred[tid] = 0.0f;
    __syncthreads();
    atomicAdd(&sred[m0+0], pm[0]);
    atomicAdd(&sred[m0+1], pm[1]);
    atomicAdd(&sred[m0+2], pm[2]);
    atomicAdd(&sred[m0+3], pm[3]);
    __syncthreads();
    if (tid < 64) sfin[tid] = logf(sred[tid]) * fr_mask[b * S_SZ + tid];
    __syncthreads();
    if (tid == 0) {
        float s = 0.0f;
        for (int i = 0; i < 64; i++) s += sfin[i];
        out[B_SZ + b] = s;
    }
}

// ---------------------------------------------------------------------------
extern "C" void kernel_launch(void* const* d_in, const int* in_sizes, int n_in,
                              void* d_out, int out_size)
{
    const float* zs      = (const float*)d_in[0];
    const int*   x_en    = (const int*)  d_in[1];
    const int*   x_fr    = (const int*)  d_in[2];
    const float* en_mask = (const float*)d_in[3];
    const float* fr_mask = (const float*)d_in[4];
    const float* W_en    = (const float*)d_in[5];
    const float* W_fr    = (const float*)d_in[6];
    const int*   pos_en  = (const int*)  d_in[7];  int P_en = in_sizes[7];
    const int*   neg_en  = (const int*)  d_in[8];  int N_en = in_sizes[8];
    const int*   pos_fr  = (const int*)  d_in[9];  int P_fr = in_sizes[9];
    const int*   neg_fr  = (const int*)  d_in[10]; int N_fr = in_sizes[10];
    const float* kap_en  = (const float*)d_in[11];
    const float* kap_fr  = (const float*)d_in[12];
    float* out = (float*)d_out;

    int C_en = P_en + N_en;
    int C_fr = P_fr + N_fr;
    int Cpad_en = ((C_en + 511) / 512) * 512;
    int Cpad_fr = ((C_fr + 511) / 512) * 512;
    if (Cpad_en > CPAD_MAX) Cpad_en = CPAD_MAX;
    if (Cpad_fr > CPAD_MAX) Cpad_fr = CPAD_MAX;

    static int smem_set = 0;
    if (!smem_set) {
        cudaFuncSetAttribute(denom_mma_kernel,
                             cudaFuncAttributeMaxDynamicSharedMemorySize, 3 * 65536);
        smem_set = 1;
    }

    prologue_kernel<<<512 + Cpad_en / 8 + Cpad_fr / 8, 256>>>(
        zs, out, W_en, pos_en, neg_en, kap_en, P_en, C_en, Cpad_en,
        W_fr, pos_fr, neg_fr, kap_fr, P_fr, C_fr, Cpad_fr);

    dim3 grid(T_TOT / 128, NSPLIT, 2);
    denom_mma_kernel<<<grid, 256, 3 * 65536>>>(Cpad_en, Cpad_fr);

    loss_kernel<<<512 + B_SZ, 256>>>(zs, x_en, en_mask, W_en,
                                     x_fr, fr_mask, W_fr, out);
}

// round 16
// speedup vs baseline: 1.1105x; 1.1105x over previous
#include <cuda_runtime.h>
#include <cuda_bf16.h>
#include <cstdint>

#define D_DIM 256
#define B_SZ  64
#define S_SZ  64
#define T_TOT 4096
#define CPAD 12288
#define NTILES 96                  /* B tiles per lang = CPAD/128 */
#define TOTAL_U (2 * 32 * NTILES)  /* 6144 tile-iterations */
#define NSM 148

#define LOG2E 1.4426950408889634f

// ---------------------------------------------------------------------------
// Device scratch (no allocs allowed)
// ---------------------------------------------------------------------------
__device__ float         g_denom[2][T_TOT];
__device__ __nv_bfloat16 g_zsb[T_TOT * D_DIM];        // bf16, pre-scaled by log2(e)
__device__ __nv_bfloat16 g_emb[2][CPAD * D_DIM];      // bf16 gathered candidates
__device__ float         g_wt[2][CPAD];

// ---------------------------------------------------------------------------
// PTX helpers (baseline sm_80 features only — no 'a'-suffix ops)
// ---------------------------------------------------------------------------
__device__ __forceinline__ uint32_t smem_to_u32(const void* p) {
    uint32_t a;
    asm("{ .reg .u64 t; cvta.to.shared.u64 t, %1; cvt.u32.u64 %0, t; }" : "=r"(a) : "l"(p));
    return a;
}
#define CP_ASYNC16(s, g) \
    asm volatile("cp.async.cg.shared.global [%0], [%1], 16;" :: "r"(s), "l"(g) : "memory")
#define CP_COMMIT() asm volatile("cp.async.commit_group;" ::: "memory")
#define CP_WAIT0()  asm volatile("cp.async.wait_group 0;" ::: "memory")
#define CP_WAIT1()  asm volatile("cp.async.wait_group 1;" ::: "memory")

#define LDSM_X4(r0, r1, r2, r3, a) \
    asm volatile("ldmatrix.sync.aligned.m8n8.x4.shared.b16 {%0,%1,%2,%3}, [%4];" \
                 : "=r"(r0), "=r"(r1), "=r"(r2), "=r"(r3) : "r"(a))

#define MMA16816(d, a0, a1, a2, a3, b0, b1) \
    asm volatile("mma.sync.aligned.m16n8k16.row.col.f32.bf16.bf16.f32 " \
                 "{%0,%1,%2,%3},{%4,%5,%6,%7},{%8,%9},{%0,%1,%2,%3};" \
                 : "+f"((d)[0]), "+f"((d)[1]), "+f"((d)[2]), "+f"((d)[3]) \
                 : "r"(a0), "r"(a1), "r"(a2), "r"(a3), "r"(b0), "r"(b1))

__device__ __forceinline__ float ex2f(float x) {
    float y;
    asm("ex2.approx.f32 %0, %1;" : "=f"(y) : "f"(x));
    return y;
}

// ---------------------------------------------------------------------------
// Merged prologue: [0,512) convert zs + zero; [512, 512+CPAD/8) gather en;
// remainder gather fr.
// ---------------------------------------------------------------------------
__device__ __forceinline__ void gather_rows(
    const float* __restrict__ W, const int* __restrict__ pos,
    const int* __restrict__ neg, const float* __restrict__ kap,
    int P, int C, int lang, int blk)
{
    int wid = threadIdx.x >> 5, lane = threadIdx.x & 31;
    int r = blk * 8 + wid;
    if (r >= CPAD) return;
    __nv_bfloat16* dst = g_emb[lang] + (size_t)r * D_DIM + lane * 8;
    if (r >= C) {
        *(uint4*)dst = make_uint4(0, 0, 0, 0);
        if (lane == 0) g_wt[lang][r] = 0.0f;
        return;
    }
    int src; float w;
    if (r < P) { src = pos[r]; w = 1.0f; }
    else       { src = neg[r - P]; w = *kap; }
    const float4* p = (const float4*)(W + (size_t)src * D_DIM) + lane * 2;
    float4 a = p[0], b = p[1];
    __nv_bfloat162 p0 = __float22bfloat162_rn(make_float2(a.x, a.y));
    __nv_bfloat162 p1 = __float22bfloat162_rn(make_float2(a.z, a.w));
    __nv_bfloat162 p2 = __float22bfloat162_rn(make_float2(b.x, b.y));
    __nv_bfloat162 p3 = __float22bfloat162_rn(make_float2(b.z, b.w));
    uint4 v;
    v.x = *(uint32_t*)&p0; v.y = *(uint32_t*)&p1;
    v.z = *(uint32_t*)&p2; v.w = *(uint32_t*)&p3;
    *(uint4*)dst = v;
    if (lane == 0) g_wt[lang][r] = w;
}

__global__ __launch_bounds__(256) void prologue_kernel(
    const float* __restrict__ zs, float* __restrict__ out,
    const float* __restrict__ W_en, const int* __restrict__ pos_en,
    const int* __restrict__ neg_en, const float* __restrict__ kap_en,
    int P_en, int C_en,
    const float* __restrict__ W_fr, const int* __restrict__ pos_fr,
    const int* __restrict__ neg_fr, const float* __restrict__ kap_fr,
    int P_fr, int C_fr)
{
    int b = blockIdx.x;
    if (b < 512) {
        int gid = b * 256 + threadIdx.x;
        if (gid < 2 * T_TOT) ((float*)g_denom)[gid] = 0.0f;
        if (gid < 2 * B_SZ) out[gid] = 0.0f;
        const float4* p = (const float4*)(zs) + gid * 2;
        float4 a = p[0], bb = p[1];
        __nv_bfloat162 p0 = __float22bfloat162_rn(make_float2(a.x * LOG2E, a.y * LOG2E));
        __nv_bfloat162 p1 = __float22bfloat162_rn(make_float2(a.z * LOG2E, a.w * LOG2E));
        __nv_bfloat162 p2 = __float22bfloat162_rn(make_float2(bb.x * LOG2E, bb.y * LOG2E));
        __nv_bfloat162 p3 = __float22bfloat162_rn(make_float2(bb.z * LOG2E, bb.w * LOG2E));
        uint4 v;
        v.x = *(uint32_t*)&p0; v.y = *(uint32_t*)&p1;
        v.z = *(uint32_t*)&p2; v.w = *(uint32_t*)&p3;
        *(uint4*)(g_zsb + (size_t)gid * 8) = v;
    } else if (b < 512 + CPAD / 8) {
        gather_rows(W_en, pos_en, neg_en, kap_en, P_en, C_en, 0, b - 512);
    } else {
        gather_rows(W_fr, pos_fr, neg_fr, kap_fr, P_fr, C_fr, 1, b - 512 - CPAD / 8);
    }
}

// ---------------------------------------------------------------------------
// SMEM tile: 128 rows x 256 bf16 (512 B/row = 32 chunks of 16B). XOR swizzle.
// ---------------------------------------------------------------------------
__device__ __forceinline__ void cp_tile(uint32_t sdst, const __nv_bfloat16* __restrict__ src, int tid) {
    #pragma unroll
    for (int t = 0; t < 16; t++) {
        int id = tid + t * 256;
        int row = id >> 5, h = id & 31;
        uint32_t s = sdst + row * 512 + ((h ^ (row & 7)) << 4);
        CP_ASYNC16(s, (const void*)(src + (size_t)row * D_DIM + h * 8));
    }
}

// ---------------------------------------------------------------------------
// Denominator GEMM via bf16 mma.sync m16n8k16, statically load-balanced:
// global work = 6144 tile-iters (2 lang x 32 Mtile x 96 btile); 148 CTAs each
// own a contiguous range (41-42 iters, vs 48 in the fixed-grid version).
// A reloaded only on (lang,Mtile) segment crossing (<=2 per CTA); row
// accumulators flushed by atomicAdd at segment boundaries (split-K safe).
// Inner loop identical to the measured-best R9 kernel (fragment double
// buffering for A and B, log2-domain ex2 epilogue).
// ---------------------------------------------------------------------------
__global__ __launch_bounds__(256, 1) void denom_mma_kernel()
{
    extern __shared__ char smem[];
    uint32_t sA  = smem_to_u32(smem);
    uint32_t sB0 = sA + 65536;
    uint32_t sB1 = sB0 + 65536;
    uint32_t bufs[2] = { sB0, sB1 };

    const int tid = threadIdx.x;
    const int wid = tid >> 5, lane = tid & 31;

    const int ustart = (int)(((long long)blockIdx.x * TOTAL_U) / NSM);
    const int uend   = (int)(((long long)(blockIdx.x + 1) * TOTAL_U) / NSM);

    int seg  = ustart / NTILES;
    int bt   = ustart % NTILES;
    int lang = seg >> 5, Mt = seg & 31;

    const int warpM = (wid >> 2) * 64;
    const int warpN = (wid & 3) * 32;
    const int g   = lane >> 3;
    const int rin = lane & 7;
    const int ga  = g >> 1;
    const int gb  = g & 1;
    const int a_row = rin + ((g & 1) << 3);
    const int b_row = rin + ((g >> 1) << 3);

    uint32_t aRow[4];
    #pragma unroll
    for (int mf = 0; mf < 4; mf++)
        aRow[mf] = sA + (warpM + mf * 16 + a_row) * 512;
    uint32_t bRowOff[2];
    #pragma unroll
    for (int nf2 = 0; nf2 < 2; nf2++)
        bRowOff[nf2] = (warpN + nf2 * 16 + b_row) * 512;

    // Initial loads: A(seg), B(ustart)
    cp_tile(sA, g_zsb + (size_t)(Mt * 128) * D_DIM, tid);
    CP_COMMIT();
    cp_tile(sB0, g_emb[lang] + (size_t)(bt * 128) * D_DIM, tid);
    CP_COMMIT();
    CP_WAIT0();
    __syncthreads();

    float rowacc[8];
    #pragma unroll
    for (int j = 0; j < 8; j++) rowacc[j] = 0.0f;
    int bcur = 0;

    for (int u = ustart; u < uend; u++) {
        const uint32_t sBc = bufs[bcur];
        const bool segEnd = (bt == NTILES - 1) || (u + 1 == uend);

        if (!segEnd) {
            cp_tile(bufs[bcur ^ 1], g_emb[lang] + (size_t)((bt + 1) * 128) * D_DIM, tid);
            CP_COMMIT();
            CP_WAIT1();
        } else {
            CP_WAIT0();
        }
        __syncthreads();

        float cc[4][4][4];
        #pragma unroll
        for (int mf = 0; mf < 4; mf++)
            #pragma unroll
            for (int nf = 0; nf < 4; nf++)
                #pragma unroll
                for (int q = 0; q < 4; q++) cc[mf][nf][q] = 0.0f;

        // k-fragment double buffer: prefetch k-step s+1 while MMAing step s.
        uint32_t ra[2][4][4], rb[2][4][2];
        {
            const uint32_t offA = (uint32_t)((ga ^ rin) << 4);
            const uint32_t offB = (uint32_t)((gb ^ rin) << 4);
            #pragma unroll
            for (int mf = 0; mf < 4; mf++)
                LDSM_X4(ra[0][mf][0], ra[0][mf][1], ra[0][mf][2], ra[0][mf][3], aRow[mf] + offA);
            #pragma unroll
            for (int nf2 = 0; nf2 < 2; nf2++) {
                uint32_t r0, r1, r2, r3;
                LDSM_X4(r0, r1, r2, r3, sBc + bRowOff[nf2] + offB);
                rb[0][nf2 * 2 + 0][0] = r0; rb[0][nf2 * 2 + 0][1] = r1;
                rb[0][nf2 * 2 + 1][0] = r2; rb[0][nf2 * 2 + 1][1] = r3;
            }
        }
        #pragma unroll
        for (int s = 0; s < 16; s++) {
            const int cb = s & 1, nb = cb ^ 1;
            if (s < 15) {
                const uint32_t offA = (uint32_t)(((2 * (s + 1) + ga) ^ rin) << 4);
                const uint32_t offB = (uint32_t)(((2 * (s + 1) + gb) ^ rin) << 4);
                #pragma unroll
                for (int mf = 0; mf < 4; mf++)
                    LDSM_X4(ra[nb][mf][0], ra[nb][mf][1], ra[nb][mf][2], ra[nb][mf][3],
                            aRow[mf] + offA);
                #pragma unroll
                for (int nf2 = 0; nf2 < 2; nf2++) {
                    uint32_t r0, r1, r2, r3;
                    LDSM_X4(r0, r1, r2, r3, sBc + bRowOff[nf2] + offB);
                    rb[nb][nf2 * 2 + 0][0] = r0; rb[nb][nf2 * 2 + 0][1] = r1;
                    rb[nb][nf2 * 2 + 1][0] = r2; rb[nb][nf2 * 2 + 1][1] = r3;
                }
            }
            #pragma unroll
            for (int mf = 0; mf < 4; mf++)
                #pragma unroll
                for (int nf = 0; nf < 4; nf++)
                    MMA16816(cc[mf][nf], ra[cb][mf][0], ra[cb][mf][1], ra[cb][mf][2],
                             ra[cb][mf][3], rb[cb][nf][0], rb[cb][nf][1]);
        }

        // Fused epilogue (log2 domain): rowacc += wt[col] * 2^score
        const float* wtp = g_wt[lang] + bt * 128 + warpN + 2 * (lane & 3);
        #pragma unroll
        for (int nf = 0; nf < 4; nf++) {
            const float w0 = wtp[nf * 8], w1 = wtp[nf * 8 + 1];
            #pragma unroll
            for (int mf = 0; mf < 4; mf++) {
                rowacc[mf * 2 + 0] += w0 * ex2f(cc[mf][nf][0]) + w1 * ex2f(cc[mf][nf][1]);
                rowacc[mf * 2 + 1] += w0 * ex2f(cc[mf][nf][2]) + w1 * ex2f(cc[mf][nf][3]);
            }
        }
        __syncthreads();   // all reads of buffers/A done before any overwrite

        if (segEnd) {
            // Flush accumulators for this (lang, Mtile) segment (split-K).
            #pragma unroll
            for (int j = 0; j < 8; j++) {
                float v = rowacc[j];
                v += __shfl_xor_sync(0xffffffffu, v, 1);
                v += __shfl_xor_sync(0xffffffffu, v, 2);
                if ((lane & 3) == 0)
                    atomicAdd(&g_denom[lang][Mt * 128 + warpM + (j >> 1) * 16 + (j & 1) * 8 + (lane >> 2)], v);
                rowacc[j] = 0.0f;
            }
            if (u + 1 < uend) {
                seg++; bt = 0; lang = seg >> 5; Mt = seg & 31;
                cp_tile(sA, g_zsb + (size_t)(Mt * 128) * D_DIM, tid);
                CP_COMMIT();
                cp_tile(bufs[bcur ^ 1], g_emb[lang], tid);
                CP_COMMIT();
                CP_WAIT0();
                __syncthreads();
                bcur ^= 1;
            }
        } else {
            bt++;
            bcur ^= 1;
        }
    }
}

// ---------------------------------------------------------------------------
// fr loss helpers (validated fp32 f32x2 path)
// ---------------------------------------------------------------------------
__device__ __forceinline__ void fma2(unsigned long long &d, unsigned long long a, unsigned long long b) {
    asm("fma.rn.f32x2 %0, %1, %2, %0;" : "+l"(d) : "l"(a), "l"(b));
}
__device__ __forceinline__ unsigned long long pack2(float lo, float hi) {
    unsigned long long r;
    asm("mov.b64 %0, {%1, %2};" : "=l"(r) : "f"(lo), "f"(hi));
    return r;
}
__device__ __forceinline__ void unpack2(unsigned long long v, float &lo, float &hi) {
    asm("mov.b64 {%0, %1}, %2;" : "=f"(lo), "=f"(hi) : "l"(v));
}

// ---------------------------------------------------------------------------
// Merged loss kernel: blocks [0,512) en (warp-per-token); [512,576) fr.
// ---------------------------------------------------------------------------
__global__ __launch_bounds__(256) void loss_kernel(
    const float* __restrict__ zs,
    const int* __restrict__ x_en, const float* __restrict__ en_mask,
    const float* __restrict__ W_en,
    const int* __restrict__ x_fr, const float* __restrict__ fr_mask,
    const float* __restrict__ W_fr,
    float* __restrict__ out)
{
    __shared__ float Fs[16][64];
    __shared__ float Zs[16][64];
    __shared__ int   fidx[64];
    __shared__ float invd[64];
    __shared__ float sred[64];
    __shared__ float sfin[64];

    if (blockIdx.x < 512) {
        int wid = threadIdx.x >> 5, lane = threadIdx.x & 31;
        int t = blockIdx.x * 8 + wid;
        const float4* z = (const float4*)(zs + (size_t)t * D_DIM) + lane * 2;
        const float4* w = (const float4*)(W_en + (size_t)x_en[t] * D_DIM) + lane * 2;
        float4 a0 = z[0], a1 = z[1], b0 = w[0], b1 = w[1];
        float s = a0.x * b0.x + a0.y * b0.y + a0.z * b0.z + a0.w * b0.w
                + a1.x * b1.x + a1.y * b1.y + a1.z * b1.z + a1.w * b1.w;
        #pragma unroll
        for (int o = 16; o > 0; o >>= 1) s += __shfl_xor_sync(0xffffffffu, s, o);
        if (lane == 0)
            atomicAdd(&out[t >> 6], (s - logf(g_denom[0][t])) * en_mask[t]);
        return;
    }

    int b = blockIdx.x - 512;
    int tid = threadIdx.x;
    int tx = tid & 15, ty = tid >> 4;
    int m0 = tx * 4, n0 = ty * 4;

    if (tid < 64) {
        fidx[tid] = x_fr[b * S_SZ + tid];
        invd[tid] = 1.0f / g_denom[1][b * S_SZ + tid];
    }
    __syncthreads();

    int lr  = tid >> 2;
    int lkc = (tid & 3) << 2;
    const float* frow = W_fr + (size_t)fidx[lr] * D_DIM + lkc;
    const float* zrow = zs   + (size_t)(b * S_SZ + lr) * D_DIM + lkc;

    unsigned long long acc2[2][4];
    #pragma unroll
    for (int p = 0; p < 2; p++)
        #pragma unroll
        for (int j = 0; j < 4; j++) acc2[p][j] = 0ull;

    for (int k0 = 0; k0 < D_DIM; k0 += 16) {
        float4 av = *(const float4*)(frow + k0);
        float4 bv = *(const float4*)(zrow + k0);
        __syncthreads();
        Fs[lkc+0][lr] = av.x; Fs[lkc+1][lr] = av.y;
        Fs[lkc+2][lr] = av.z; Fs[lkc+3][lr] = av.w;
        Zs[lkc+0][lr] = bv.x; Zs[lkc+1][lr] = bv.y;
        Zs[lkc+2][lr] = bv.z; Zs[lkc+3][lr] = bv.w;
        __syncthreads();
        #pragma unroll
        for (int k = 0; k < 16; k++) {
            ulonglong2 a = *(const ulonglong2*)&Fs[k][m0];
            float4     bq = *(const float4*)&Zs[k][n0];
            unsigned long long b0 = pack2(bq.x, bq.x);
            unsigned long long b1 = pack2(bq.y, bq.y);
            unsigned long long b2 = pack2(bq.z, bq.z);
            unsigned long long b3 = pack2(bq.w, bq.w);
            fma2(acc2[0][0], a.x, b0); fma2(acc2[0][1], a.x, b1);
            fma2(acc2[0][2], a.x, b2); fma2(acc2[0][3], a.x, b3);
            fma2(acc2[1][0], a.y, b0); fma2(acc2[1][1], a.y, b1);
            fma2(acc2[1][2], a.y, b2); fma2(acc2[1][3], a.y, b3);
        }
    }

    float w0 = invd[n0], w1 = invd[n0+1], w2 = invd[n0+2], w3 = invd[n0+3];
    float pm[4];
    #pragma unroll
    for (int p = 0; p < 2; p++) {
        float s0a,s0b,s1a,s1b,s2a,s2b,s3a,s3b;
        unpack2(acc2[p][0], s0a, s0b);
        unpack2(acc2[p][1], s1a, s1b);
        unpack2(acc2[p][2], s2a, s2b);
        unpack2(acc2[p][3], s3a, s3b);
        pm[2*p+0] = w0*__expf(s0a) + w1*__expf(s1a) + w2*__expf(s2a) + w3*__expf(s3a);
        pm[2*p+1] = w0*__expf(s0b) + w1*__expf(s1b) + w2*__expf(s2b) + w3*__expf(s3b);
    }

    __syncthreads();
    if (tid < 64) sred[tid] = 0.0f;
    __syncthreads();
    atomicAdd(&sred[m0+0], pm[0]);
    atomicAdd(&sred[m0+1], pm[1]);
    atomicAdd(&sred[m0+2], pm[2]);
    atomicAdd(&sred[m0+3], pm[3]);
    __syncthreads();
    if (tid < 64) sfin[tid] = logf(sred[tid]) * fr_mask[b * S_SZ + tid];
    __syncthreads();
    if (tid == 0) {
        float s = 0.0f;
        for (int i = 0; i < 64; i++) s += sfin[i];
        out[B_SZ + b] = s;
    }
}

// ---------------------------------------------------------------------------
extern "C" void kernel_launch(void* const* d_in, const int* in_sizes, int n_in,
                              void* d_out, int out_size)
{
    const float* zs      = (const float*)d_in[0];
    const int*   x_en    = (const int*)  d_in[1];
    const int*   x_fr    = (const int*)  d_in[2];
    const float* en_mask = (const float*)d_in[3];
    const float* fr_mask = (const float*)d_in[4];
    const float* W_en    = (const float*)d_in[5];
    const float* W_fr    = (const float*)d_in[6];
    const int*   pos_en  = (const int*)  d_in[7];  int P_en = in_sizes[7];
    const int*   neg_en  = (const int*)  d_in[8];  int N_en = in_sizes[8];
    const int*   pos_fr  = (const int*)  d_in[9];  int P_fr = in_sizes[9];
    const int*   neg_fr  = (const int*)  d_in[10]; int N_fr = in_sizes[10];
    const float* kap_en  = (const float*)d_in[11];
    const float* kap_fr  = (const float*)d_in[12];
    float* out = (float*)d_out;

    int C_en = P_en + N_en;  if (C_en > CPAD) C_en = CPAD;
    int C_fr = P_fr + N_fr;  if (C_fr > CPAD) C_fr = CPAD;

    static int smem_set = 0;
    if (!smem_set) {
        cudaFuncSetAttribute(denom_mma_kernel,
                             cudaFuncAttributeMaxDynamicSharedMemorySize, 3 * 65536);
        smem_set = 1;
    }

    prologue_kernel<<<512 + 2 * (CPAD / 8), 256>>>(
        zs, out, W_en, pos_en, neg_en, kap_en, P_en, C_en,
        W_fr, pos_fr, neg_fr, kap_fr, P_fr, C_fr);

    denom_mma_kernel<<<NSM, 256, 3 * 65536>>>();

    loss_kernel<<<512 + B_SZ, 256>>>(zs, x_en, en_mask, W_en,
                                     x_fr, fr_mask, W_fr, out);
}

// round 17
// speedup vs baseline: 1.1208x; 1.0092x over previous
#include <cuda_runtime.h>
#include <cuda_bf16.h>
#include <cstdint>

#define D_DIM 256
#define B_SZ  64
#define S_SZ  64
#define T_TOT 4096
#define CPAD 12288
#define NTILES 96                  /* B tiles per lang = CPAD/128 */
#define TOTAL_U (2 * 32 * NTILES)  /* 6144 tile-iterations */
#define NSM 148

#define LOG2E 1.4426950408889634f

// ---------------------------------------------------------------------------
// Device scratch (no allocs allowed)
// ---------------------------------------------------------------------------
__device__ float         g_denom[2][T_TOT];
__device__ __nv_bfloat16 g_zsb[T_TOT * D_DIM];        // bf16, pre-scaled by log2(e)
__device__ __nv_bfloat16 g_emb[2][CPAD * D_DIM];      // bf16 gathered candidates
__device__ float         g_wt[2][CPAD];

// ---------------------------------------------------------------------------
// PTX helpers (baseline sm_80 features only — no 'a'-suffix ops)
// ---------------------------------------------------------------------------
__device__ __forceinline__ uint32_t smem_to_u32(const void* p) {
    uint32_t a;
    asm("{ .reg .u64 t; cvta.to.shared.u64 t, %1; cvt.u32.u64 %0, t; }" : "=r"(a) : "l"(p));
    return a;
}
#define CP_ASYNC16(s, g) \
    asm volatile("cp.async.cg.shared.global [%0], [%1], 16;" :: "r"(s), "l"(g) : "memory")
#define CP_COMMIT() asm volatile("cp.async.commit_group;" ::: "memory")
#define CP_WAIT0()  asm volatile("cp.async.wait_group 0;" ::: "memory")
#define CP_WAIT1()  asm volatile("cp.async.wait_group 1;" ::: "memory")

#define LDSM_X4(r0, r1, r2, r3, a) \
    asm volatile("ldmatrix.sync.aligned.m8n8.x4.shared.b16 {%0,%1,%2,%3}, [%4];" \
                 : "=r"(r0), "=r"(r1), "=r"(r2), "=r"(r3) : "r"(a))

#define MMA16816(d, a0, a1, a2, a3, b0, b1) \
    asm volatile("mma.sync.aligned.m16n8k16.row.col.f32.bf16.bf16.f32 " \
                 "{%0,%1,%2,%3},{%4,%5,%6,%7},{%8,%9},{%0,%1,%2,%3};" \
                 : "+f"((d)[0]), "+f"((d)[1]), "+f"((d)[2]), "+f"((d)[3]) \
                 : "r"(a0), "r"(a1), "r"(a2), "r"(a3), "r"(b0), "r"(b1))

__device__ __forceinline__ float ex2f(float x) {
    float y;
    asm("ex2.approx.f32 %0, %1;" : "=f"(y) : "f"(x));
    return y;
}

// ---------------------------------------------------------------------------
// Merged prologue: [0,512) convert zs + zero; [512, 512+CPAD/16) gather en;
// remainder gather fr. Gather: warp handles TWO rows with loads hoisted
// (MLP 4/thread) to halve exposed DRAM latency.
// ---------------------------------------------------------------------------
__device__ __forceinline__ void gather_rows2(
    const float* __restrict__ W, const int* __restrict__ pos,
    const int* __restrict__ neg, const float* __restrict__ kap,
    int P, int C, int lang, int blk)
{
    int wid = threadIdx.x >> 5, lane = threadIdx.x & 31;
    int r0 = blk * 16 + wid * 2;

    int   rr[2]  = { r0, r0 + 1 };
    bool  pad[2];
    float w[2];
    const float4* p[2];
    #pragma unroll
    for (int j = 0; j < 2; j++) {
        int r = rr[j];
        pad[j] = (r >= C);
        if (!pad[j]) {
            int src;
            if (r < P) { src = pos[r]; w[j] = 1.0f; }
            else       { src = neg[r - P]; w[j] = *kap; }
            p[j] = (const float4*)(W + (size_t)src * D_DIM) + lane * 2;
        }
    }
    // Hoist all 4 loads
    float4 a0, b0, a1, b1;
    if (!pad[0]) { a0 = p[0][0]; b0 = p[0][1]; }
    if (!pad[1]) { a1 = p[1][0]; b1 = p[1][1]; }

    #pragma unroll
    for (int j = 0; j < 2; j++) {
        int r = rr[j];
        __nv_bfloat16* dst = g_emb[lang] + (size_t)r * D_DIM + lane * 8;
        if (pad[j]) {
            *(uint4*)dst = make_uint4(0, 0, 0, 0);
            if (lane == 0) g_wt[lang][r] = 0.0f;
            continue;
        }
        float4 a = j ? a1 : a0;
        float4 b = j ? b1 : b0;
        __nv_bfloat162 p0 = __float22bfloat162_rn(make_float2(a.x, a.y));
        __nv_bfloat162 p1 = __float22bfloat162_rn(make_float2(a.z, a.w));
        __nv_bfloat162 p2 = __float22bfloat162_rn(make_float2(b.x, b.y));
        __nv_bfloat162 p3 = __float22bfloat162_rn(make_float2(b.z, b.w));
        uint4 v;
        v.x = *(uint32_t*)&p0; v.y = *(uint32_t*)&p1;
        v.z = *(uint32_t*)&p2; v.w = *(uint32_t*)&p3;
        *(uint4*)dst = v;
        if (lane == 0) g_wt[lang][r] = w[j];
    }
}

__global__ __launch_bounds__(256) void prologue_kernel(
    const float* __restrict__ zs, float* __restrict__ out,
    const float* __restrict__ W_en, const int* __restrict__ pos_en,
    const int* __restrict__ neg_en, const float* __restrict__ kap_en,
    int P_en, int C_en,
    const float* __restrict__ W_fr, const int* __restrict__ pos_fr,
    const int* __restrict__ neg_fr, const float* __restrict__ kap_fr,
    int P_fr, int C_fr)
{
    int b = blockIdx.x;
    if (b < 512) {
        int gid = b * 256 + threadIdx.x;
        if (gid < 2 * T_TOT) ((float*)g_denom)[gid] = 0.0f;
        if (gid < 2 * B_SZ) out[gid] = 0.0f;
        const float4* p = (const float4*)(zs) + gid * 2;
        float4 a = p[0], bb = p[1];
        __nv_bfloat162 p0 = __float22bfloat162_rn(make_float2(a.x * LOG2E, a.y * LOG2E));
        __nv_bfloat162 p1 = __float22bfloat162_rn(make_float2(a.z * LOG2E, a.w * LOG2E));
        __nv_bfloat162 p2 = __float22bfloat162_rn(make_float2(bb.x * LOG2E, bb.y * LOG2E));
        __nv_bfloat162 p3 = __float22bfloat162_rn(make_float2(bb.z * LOG2E, bb.w * LOG2E));
        uint4 v;
        v.x = *(uint32_t*)&p0; v.y = *(uint32_t*)&p1;
        v.z = *(uint32_t*)&p2; v.w = *(uint32_t*)&p3;
        *(uint4*)(g_zsb + (size_t)gid * 8) = v;
    } else if (b < 512 + CPAD / 16) {
        gather_rows2(W_en, pos_en, neg_en, kap_en, P_en, C_en, 0, b - 512);
    } else {
        gather_rows2(W_fr, pos_fr, neg_fr, kap_fr, P_fr, C_fr, 1, b - 512 - CPAD / 16);
    }
}

// ---------------------------------------------------------------------------
// SMEM tile: 128 rows x 256 bf16 (512 B/row = 32 chunks of 16B). XOR swizzle.
// ---------------------------------------------------------------------------
__device__ __forceinline__ void cp_tile(uint32_t sdst, const __nv_bfloat16* __restrict__ src, int tid) {
    #pragma unroll
    for (int t = 0; t < 16; t++) {
        int id = tid + t * 256;
        int row = id >> 5, h = id & 31;
        uint32_t s = sdst + row * 512 + ((h ^ (row & 7)) << 4);
        CP_ASYNC16(s, (const void*)(src + (size_t)row * D_DIM + h * 8));
    }
}

// ---------------------------------------------------------------------------
// Denominator GEMM via bf16 mma.sync m16n8k16, statically load-balanced
// (R16 winner). Added: 3-buffer rotation at segment boundaries — the next
// segment's A tile is prefetched into the free B buffer during the last
// B-tile's k-loop, so only the next B0 load is exposed at the crossing.
// ---------------------------------------------------------------------------
__global__ __launch_bounds__(256, 1) void denom_mma_kernel()
{
    extern __shared__ char smem[];
    uint32_t base = smem_to_u32(smem);
    uint32_t bufs[3] = { base, base + 65536, base + 2 * 65536 };

    const int tid = threadIdx.x;
    const int wid = tid >> 5, lane = tid & 31;

    const int ustart = (int)(((long long)blockIdx.x * TOTAL_U) / NSM);
    const int uend   = (int)(((long long)(blockIdx.x + 1) * TOTAL_U) / NSM);

    int seg  = ustart / NTILES;
    int bt   = ustart % NTILES;
    int lang = seg >> 5, Mt = seg & 31;

    const int warpM = (wid >> 2) * 64;
    const int warpN = (wid & 3) * 32;
    const int g   = lane >> 3;
    const int rin = lane & 7;
    const int ga  = g >> 1;
    const int gb  = g & 1;
    const int a_row = rin + ((g & 1) << 3);
    const int b_row = rin + ((g >> 1) << 3);

    uint32_t aRowOff[4];
    #pragma unroll
    for (int mf = 0; mf < 4; mf++)
        aRowOff[mf] = (warpM + mf * 16 + a_row) * 512;
    uint32_t bRowOff[2];
    #pragma unroll
    for (int nf2 = 0; nf2 < 2; nf2++)
        bRowOff[nf2] = (warpN + nf2 * 16 + b_row) * 512;

    int aIdx = 0, bcur = 1, bother = 2;

    // Initial loads: A(seg), B(ustart)
    cp_tile(bufs[aIdx], g_zsb + (size_t)(Mt * 128) * D_DIM, tid);
    CP_COMMIT();
    cp_tile(bufs[bcur], g_emb[lang] + (size_t)(bt * 128) * D_DIM, tid);
    CP_COMMIT();
    CP_WAIT0();
    __syncthreads();

    float rowacc[8];
    #pragma unroll
    for (int j = 0; j < 8; j++) rowacc[j] = 0.0f;

    for (int u = ustart; u < uend; u++) {
        const uint32_t sBc = bufs[bcur];
        const uint32_t aBase = bufs[aIdx];
        const bool segEnd = (bt == NTILES - 1) || (u + 1 == uend);

        if (!segEnd) {
            cp_tile(bufs[bother], g_emb[lang] + (size_t)((bt + 1) * 128) * D_DIM, tid);
            CP_COMMIT();
            CP_WAIT1();
        } else if (u + 1 < uend) {
            // Prefetch NEXT segment's A into the free B buffer (covered by k-loop).
            int nseg = seg + 1;
            int nMt = nseg & 31;
            cp_tile(bufs[bother], g_zsb + (size_t)(nMt * 128) * D_DIM, tid);
            CP_COMMIT();
            CP_WAIT1();
        } else {
            CP_WAIT0();
        }
        __syncthreads();

        float cc[4][4][4];
        #pragma unroll
        for (int mf = 0; mf < 4; mf++)
            #pragma unroll
            for (int nf = 0; nf < 4; nf++)
                #pragma unroll
                for (int q = 0; q < 4; q++) cc[mf][nf][q] = 0.0f;

        // k-fragment double buffer: prefetch k-step s+1 while MMAing step s.
        uint32_t ra[2][4][4], rb[2][4][2];
        {
            const uint32_t offA = (uint32_t)((ga ^ rin) << 4);
            const uint32_t offB = (uint32_t)((gb ^ rin) << 4);
            #pragma unroll
            for (int mf = 0; mf < 4; mf++)
                LDSM_X4(ra[0][mf][0], ra[0][mf][1], ra[0][mf][2], ra[0][mf][3],
                        aBase + aRowOff[mf] + offA);
            #pragma unroll
            for (int nf2 = 0; nf2 < 2; nf2++) {
                uint32_t r0, r1, r2, r3;
                LDSM_X4(r0, r1, r2, r3, sBc + bRowOff[nf2] + offB);
                rb[0][nf2 * 2 + 0][0] = r0; rb[0][nf2 * 2 + 0][1] = r1;
                rb[0][nf2 * 2 + 1][0] = r2; rb[0][nf2 * 2 + 1][1] = r3;
            }
        }
        #pragma unroll
        for (int s = 0; s < 16; s++) {
            const int cb = s & 1, nb = cb ^ 1;
            if (s < 15) {
                const uint32_t offA = (uint32_t)(((2 * (s + 1) + ga) ^ rin) << 4);
                const uint32_t offB = (uint32_t)(((2 * (s + 1) + gb) ^ rin) << 4);
                #pragma unroll
                for (int mf = 0; mf < 4; mf++)
                    LDSM_X4(ra[nb][mf][0], ra[nb][mf][1], ra[nb][mf][2], ra[nb][mf][3],
                            aBase + aRowOff[mf] + offA);
                #pragma unroll
                for (int nf2 = 0; nf2 < 2; nf2++) {
                    uint32_t r0, r1, r2, r3;
                    LDSM_X4(r0, r1, r2, r3, sBc + bRowOff[nf2] + offB);
                    rb[nb][nf2 * 2 + 0][0] = r0; rb[nb][nf2 * 2 + 0][1] = r1;
                    rb[nb][nf2 * 2 + 1][0] = r2; rb[nb][nf2 * 2 + 1][1] = r3;
                }
            }
            #pragma unroll
            for (int mf = 0; mf < 4; mf++)
                #pragma unroll
                for (int nf = 0; nf < 4; nf++)
                    MMA16816(cc[mf][nf], ra[cb][mf][0], ra[cb][mf][1], ra[cb][mf][2],
                             ra[cb][mf][3], rb[cb][nf][0], rb[cb][nf][1]);
        }

        // Fused epilogue (log2 domain): rowacc += wt[col] * 2^score
        const float* wtp = g_wt[lang] + bt * 128 + warpN + 2 * (lane & 3);
        #pragma unroll
        for (int nf = 0; nf < 4; nf++) {
            const float w0 = wtp[nf * 8], w1 = wtp[nf * 8 + 1];
            #pragma unroll
            for (int mf = 0; mf < 4; mf++) {
                rowacc[mf * 2 + 0] += w0 * ex2f(cc[mf][nf][0]) + w1 * ex2f(cc[mf][nf][1]);
                rowacc[mf * 2 + 1] += w0 * ex2f(cc[mf][nf][2]) + w1 * ex2f(cc[mf][nf][3]);
            }
        }
        __syncthreads();   // all reads of buffers done before any overwrite

        if (segEnd) {
            // Flush accumulators for this (lang, Mtile) segment (split-K).
            #pragma unroll
            for (int j = 0; j < 8; j++) {
                float v = rowacc[j];
                v += __shfl_xor_sync(0xffffffffu, v, 1);
                v += __shfl_xor_sync(0xffffffffu, v, 2);
                if ((lane & 3) == 0)
                    atomicAdd(&g_denom[lang][Mt * 128 + warpM + (j >> 1) * 16 + (j & 1) * 8 + (lane >> 2)], v);
                rowacc[j] = 0.0f;
            }
            if (u + 1 < uend) {
                seg++; bt = 0; lang = seg >> 5; Mt = seg & 31;
                // Next segment's A is already in bufs[bother] (prefetched).
                // Load its B0 into the old A buffer; only this load is exposed.
                cp_tile(bufs[aIdx], g_emb[lang], tid);
                CP_COMMIT();
                CP_WAIT0();
                __syncthreads();
                int oldA = aIdx;
                aIdx = bother;
                bcur = oldA;
                bother = (0 + 1 + 2) - aIdx - bcur;
            }
        } else {
            bt++;
            int t2 = bcur; bcur = bother; bother = t2;
        }
    }
}

// ---------------------------------------------------------------------------
// fr loss helpers (validated fp32 f32x2 path)
// ---------------------------------------------------------------------------
__device__ __forceinline__ void fma2(unsigned long long &d, unsigned long long a, unsigned long long b) {
    asm("fma.rn.f32x2 %0, %1, %2, %0;" : "+l"(d) : "l"(a), "l"(b));
}
__device__ __forceinline__ unsigned long long pack2(float lo, float hi) {
    unsigned long long r;
    asm("mov.b64 %0, {%1, %2};" : "=l"(r) : "f"(lo), "f"(hi));
    return r;
}
__device__ __forceinline__ void unpack2(unsigned long long v, float &lo, float &hi) {
    asm("mov.b64 {%0, %1}, %2;" : "=f"(lo), "=f"(hi) : "l"(v));
}

// ---------------------------------------------------------------------------
// Merged loss kernel: blocks [0,512) en (warp-per-token); [512,576) fr.
// ---------------------------------------------------------------------------
__global__ __launch_bounds__(256) void loss_kernel(
    const float* __restrict__ zs,
    const int* __restrict__ x_en, const float* __restrict__ en_mask,
    const float* __restrict__ W_en,
    const int* __restrict__ x_fr, const float* __restrict__ fr_mask,
    const float* __restrict__ W_fr,
    float* __restrict__ out)
{
    __shared__ float Fs[16][64];
    __shared__ float Zs[16][64];
    __shared__ int   fidx[64];
    __shared__ float invd[64];
    __shared__ float sred[64];
    __shared__ float sfin[64];

    if (blockIdx.x < 512) {
        int wid = threadIdx.x >> 5, lane = threadIdx.x & 31;
        int t = blockIdx.x * 8 + wid;
        const float4* z = (const float4*)(zs + (size_t)t * D_DIM) + lane * 2;
        const float4* w = (const float4*)(W_en + (size_t)x_en[t] * D_DIM) + lane * 2;
        float4 a0 = z[0], a1 = z[1], b0 = w[0], b1 = w[1];
        float s = a0.x * b0.x + a0.y * b0.y + a0.z * b0.z + a0.w * b0.w
                + a1.x * b1.x + a1.y * b1.y + a1.z * b1.z + a1.w * b1.w;
        #pragma unroll
        for (int o = 16; o > 0; o >>= 1) s += __shfl_xor_sync(0xffffffffu, s, o);
        if (lane == 0)
            atomicAdd(&out[t >> 6], (s - logf(g_denom[0][t])) * en_mask[t]);
        return;
    }

    int b = blockIdx.x - 512;
    int tid = threadIdx.x;
    int tx = tid & 15, ty = tid >> 4;
    int m0 = tx * 4, n0 = ty * 4;

    if (tid < 64) {
        fidx[tid] = x_fr[b * S_SZ + tid];
        invd[tid] = 1.0f / g_denom[1][b * S_SZ + tid];
    }
    __syncthreads();

    int lr  = tid >> 2;
    int lkc = (tid & 3) << 2;
    const float* frow = W_fr + (size_t)fidx[lr] * D_DIM + lkc;
    const float* zrow = zs   + (size_t)(b * S_SZ + lr) * D_DIM + lkc;

    unsigned long long acc2[2][4];
    #pragma unroll
    for (int p = 0; p < 2; p++)
        #pragma unroll
        for (int j = 0; j < 4; j++) acc2[p][j] = 0ull;

    for (int k0 = 0; k0 < D_DIM; k0 += 16) {
        float4 av = *(const float4*)(frow + k0);
        float4 bv = *(const float4*)(zrow + k0);
        __syncthreads();
        Fs[lkc+0][lr] = av.x; Fs[lkc+1][lr] = av.y;
        Fs[lkc+2][lr] = av.z; Fs[lkc+3][lr] = av.w;
        Zs[lkc+0][lr] = bv.x; Zs[lkc+1][lr] = bv.y;
        Zs[lkc+2][lr] = bv.z; Zs[lkc+3][lr] = bv.w;
        __syncthreads();
        #pragma unroll
        for (int k = 0; k < 16; k++) {
            ulonglong2 a = *(const ulonglong2*)&Fs[k][m0];
            float4     bq = *(const float4*)&Zs[k][n0];
            unsigned long long b0 = pack2(bq.x, bq.x);
            unsigned long long b1 = pack2(bq.y, bq.y);
            unsigned long long b2 = pack2(bq.z, bq.z);
            unsigned long long b3 = pack2(bq.w, bq.w);
            fma2(acc2[0][0], a.x, b0); fma2(acc2[0][1], a.x, b1);
            fma2(acc2[0][2], a.x, b2); fma2(acc2[0][3], a.x, b3);
            fma2(acc2[1][0], a.y, b0); fma2(acc2[1][1], a.y, b1);
            fma2(acc2[1][2], a.y, b2); fma2(acc2[1][3], a.y, b3);
        }
    }

    float w0 = invd[n0], w1 = invd[n0+1], w2 = invd[n0+2], w3 = invd[n0+3];
    float pm[4];
    #pragma unroll
    for (int p = 0; p < 2; p++) {
        float s0a,s0b,s1a,s1b,s2a,s2b,s3a,s3b;
        unpack2(acc2[p][0], s0a, s0b);
        unpack2(acc2[p][1], s1a, s1b);
        unpack2(acc2[p][2], s2a, s2b);
        unpack2(acc2[p][3], s3a, s3b);
        pm[2*p+0] = w0*__expf(s0a) + w1*__expf(s1a) + w2*__expf(s2a) + w3*__expf(s3a);
        pm[2*p+1] = w0*__expf(s0b) + w1*__expf(s1b) + w2*__expf(s2b) + w3*__expf(s3b);
    }

    __syncthreads();
    if (tid < 64) sred[tid] = 0.0f;
    __syncthreads();
    atomicAdd(&sred[m0+0], pm[0]);
    atomicAdd(&sred[m0+1], pm[1]);
    atomicAdd(&sred[m0+2], pm[2]);
    atomicAdd(&sred[m0+3], pm[3]);
    __syncthreads();
    if (tid < 64) sfin[tid] = logf(sred[tid]) * fr_mask[b * S_SZ + tid];
    __syncthreads();
    if (tid == 0) {
        float s = 0.0f;
        for (int i = 0; i < 64; i++) s += sfin[i];
        out[B_SZ + b] = s;
    }
}

// ---------------------------------------------------------------------------
extern "C" void kernel_launch(void* const* d_in, const int* in_sizes, int n_in,
                              void* d_out, int out_size)
{
    const float* zs      = (const float*)d_in[0];
    const int*   x_en    = (const int*)  d_in[1];
    const int*   x_fr    = (const int*)  d_in[2];
    const float* en_mask = (const float*)d_in[3];
    const float* fr_mask = (const float*)d_in[4];
    const float* W_en    = (const float*)d_in[5];
    const float* W_fr    = (const float*)d_in[6];
    const int*   pos_en  = (const int*)  d_in[7];  int P_en = in_sizes[7];
    const int*   neg_en  = (const int*)  d_in[8];  int N_en = in_sizes[8];
    const int*   pos_fr  = (const int*)  d_in[9];  int P_fr = in_sizes[9];
    const int*   neg_fr  = (const int*)  d_in[10]; int N_fr = in_sizes[10];
    const float* kap_en  = (const float*)d_in[11];
    const float* kap_fr  = (const float*)d_in[12];
    float* out = (float*)d_out;

    int C_en = P_en + N_en;  if (C_en > CPAD) C_en = CPAD;
    int C_fr = P_fr + N_fr;  if (C_fr > CPAD) C_fr = CPAD;

    static int smem_set = 0;
    if (!smem_set) {
        cudaFuncSetAttribute(denom_mma_kernel,
                             cudaFuncAttributeMaxDynamicSharedMemorySize, 3 * 65536);
        smem_set = 1;
    }

    prologue_kernel<<<512 + 2 * (CPAD / 16), 256>>>(
        zs, out, W_en, pos_en, neg_en, kap_en, P_en, C_en,
        W_fr, pos_fr, neg_fr, kap_fr, P_fr, C_fr);

    denom_mma_kernel<<<NSM, 256, 3 * 65536>>>();

    loss_kernel<<<512 + B_SZ, 256>>>(zs, x_en, en_mask, W_en,
                                     x_fr, fr_mask, W_fr, out);
}